// round 1
// baseline (speedup 1.0000x reference)
#include <cuda_runtime.h>
#include <math.h>

// ---------------- problem constants ----------------
#define NN    8192
#define EE    262144
#define HID   128
#define NRBF  50
#define RBF_P 52          // padded rbf row (16B-friendly)
#define NLAY  6

// ---------------- device scratch (static, no runtime allocs) ----------------
__device__ float g_rbf[(size_t)EE * RBF_P];   // sorted-order rbf, padded
__device__ float g_cut[EE];                   // sorted-order cutoff
__device__ float g_cutm[EE];                  // cutoff * (row!=col)  (NeighborEmbedding mask)
__device__ int   g_srow[EE];                  // sorted source index
__device__ int   g_sdst[EE];                  // sorted destination index
__device__ int   g_perm[EE];                  // sort permutation
__device__ int   g_cnt[NN];                   // histogram
__device__ int   g_offm[NN];                  // mutable cursor (exclusive prefix)
__device__ float g_x  [NN * HID];
__device__ float g_h  [NN * HID];
__device__ float g_h2 [NN * HID];
__device__ float g_agg[NN * HID];
__device__ float g_nex[NN * HID];             // ne_emb[z]

// ---------------- small helper kernels ----------------
__global__ void k_zero_cnt() {
    int i = blockIdx.x * blockDim.x + threadIdx.x;
    if (i < NN) g_cnt[i] = 0;
}

__global__ void k_zero_agg() {
    int i = blockIdx.x * blockDim.x + threadIdx.x;
    if (i < NN * HID) g_agg[i] = 0.f;
}

__global__ void k_hist(const int* __restrict__ ei) {
    int e = blockIdx.x * blockDim.x + threadIdx.x;
    if (e < EE) atomicAdd(&g_cnt[ei[EE + e]], 1);
}

// single-block exclusive scan of g_cnt (8192 = 1024 threads * 8)
__global__ void k_scan() {
    __shared__ int part[1024];
    int t = threadIdx.x;
    int base = t * 8;
    int loc[8];
    int s = 0;
#pragma unroll
    for (int i = 0; i < 8; i++) { loc[i] = s; s += g_cnt[base + i]; }
    part[t] = s;
    __syncthreads();
    int val = s;
    for (int off = 1; off < 1024; off <<= 1) {
        int v = (t >= off) ? part[t - off] : 0;
        __syncthreads();
        val += v;
        part[t] = val;
        __syncthreads();
    }
    int pre = (t == 0) ? 0 : part[t - 1];
#pragma unroll
    for (int i = 0; i < 8; i++) g_offm[base + i] = pre + loc[i];
}

__global__ void k_place(const int* __restrict__ ei) {
    int e = blockIdx.x * blockDim.x + threadIdx.x;
    if (e < EE) {
        int c = ei[EE + e];
        int p = atomicAdd(&g_offm[c], 1);
        g_perm[p] = e;
    }
}

// one warp per sorted edge: rbf (50 + pad), cut, masked cut, srow/sdst
__global__ void k_build(const int* __restrict__ ei, const float* __restrict__ ew,
                        const float* __restrict__ means, const float* __restrict__ betas) {
    int warp = (blockIdx.x * blockDim.x + threadIdx.x) >> 5;
    int lane = threadIdx.x & 31;
    if (warp >= EE) return;
    int e = g_perm[warp];
    int r = ei[e];
    int c = ei[EE + e];
    float d = ew[e];
    float cut = 0.5f * (cosf(d * 0.628318530717958647692f) + 1.0f);
    if (!(d < 5.0f)) cut = 0.f;
    float ex = __expf(-d);                       // ALPHA=1, START=0
    size_t ro = (size_t)warp * RBF_P;
    {
        float m = means[lane], b = betas[lane];  // lane < 32 < 50
        float v = ex - m;
        g_rbf[ro + lane] = cut * __expf(-b * v * v);
    }
    int k2 = lane + 32;
    if (k2 < NRBF) {
        float m = means[k2], b = betas[k2];
        float v = ex - m;
        g_rbf[ro + k2] = cut * __expf(-b * v * v);
    } else if (k2 < RBF_P) {
        g_rbf[ro + k2] = 0.f;                    // pad
    }
    if (lane == 0) {
        g_cut[warp]  = cut;
        g_cutm[warp] = (r != c) ? cut : 0.f;
        g_srow[warp] = r;
        g_sdst[warp] = c;
    }
}

__global__ void k_gather(const int* __restrict__ z, const float* __restrict__ emb,
                         const float* __restrict__ neemb) {
    int i = blockIdx.x * blockDim.x + threadIdx.x;
    if (i >= NN * HID) return;
    int n = i >> 7, c = i & 127;
    int zi = z[n];
    g_x[i]   = emb[zi * HID + c];
    g_nex[i] = neemb[zi * HID + c];
}

// ---------------- fused edge MLP + segmented aggregation ----------------
// NE=1: W = (rbf@W1 + b1) * cutm ; msg = nex[row]*W
// NE=0: Wf = (silu(rbf@W1+b1)@W2 + b2) * cut ; msg = h[row]*Wf
template <int NE>
__global__ void __launch_bounds__(512, 1)
k_edge(const float* __restrict__ W1g, const float* __restrict__ b1g,
       const float* __restrict__ W2g, const float* __restrict__ b2g) {
    extern __shared__ float sm[];
    const int W1SZ = NRBF * HID;                 // 6400
    const int W2SZ = NE ? 0 : HID * HID;         // 16384
    float* sW1  = sm;
    float* sW2  = sW1 + W1SZ;
    float* sRbf = sW2 + W2SZ;                    // 128 x 52
    float* sBuf = sRbf + 128 * RBF_P;            // 128 x 132
    float* sB1  = sBuf + 128 * 132;
    float* sB2  = sB1 + 128;
    float* sCut = sB2 + 128;
    int*   sRow = (int*)(sCut + 128);
    int*   sDst = sRow + 128;

    int tid = threadIdx.x;
    long ebase = (long)blockIdx.x * 128;

    for (int i = tid; i < W1SZ; i += 512) sW1[i] = W1g[i];
    if (!NE)
        for (int i = tid; i < HID * HID; i += 512) sW2[i] = W2g[i];
    for (int i = tid; i < 128 * RBF_P; i += 512) sRbf[i] = g_rbf[ebase * RBF_P + i];
    if (tid < 128) {
        sB1[tid]  = b1g[tid];
        sB2[tid]  = NE ? 0.f : b2g[tid];
        sCut[tid] = NE ? g_cutm[ebase + tid] : g_cut[ebase + tid];
        sRow[tid] = g_srow[ebase + tid];
        sDst[tid] = g_sdst[ebase + tid];
    }
    __syncthreads();

    int tx = tid & 15, ty = tid >> 4;            // 16 x 32 thread grid
    int r0 = ty * 4, c0 = tx * 8;                // 4 rows x 8 cols per thread
    float acc[4][8];
#pragma unroll
    for (int i = 0; i < 4; i++)
#pragma unroll
        for (int j = 0; j < 8; j++) acc[i][j] = 0.f;

    // GEMM1: rbf[128,50] @ W1[50,128]
#pragma unroll 2
    for (int k = 0; k < NRBF; k++) {
        float a[4];
#pragma unroll
        for (int i = 0; i < 4; i++) a[i] = sRbf[(r0 + i) * RBF_P + k];
        float4 bA = *(const float4*)&sW1[k * HID + c0];
        float4 bB = *(const float4*)&sW1[k * HID + c0 + 4];
        float b[8] = {bA.x, bA.y, bA.z, bA.w, bB.x, bB.y, bB.z, bB.w};
#pragma unroll
        for (int i = 0; i < 4; i++)
#pragma unroll
            for (int j = 0; j < 8; j++) acc[i][j] = fmaf(a[i], b[j], acc[i][j]);
    }

    if (NE) {
#pragma unroll
        for (int i = 0; i < 4; i++) {
            float cu = sCut[r0 + i];
#pragma unroll
            for (int j = 0; j < 8; j++)
                sBuf[(r0 + i) * 132 + c0 + j] = (acc[i][j] + sB1[c0 + j]) * cu;
        }
        __syncthreads();
    } else {
        // silu -> smem
#pragma unroll
        for (int i = 0; i < 4; i++)
#pragma unroll
            for (int j = 0; j < 8; j++) {
                float v = acc[i][j] + sB1[c0 + j];
                sBuf[(r0 + i) * 132 + c0 + j] = v / (1.0f + __expf(-v));
            }
        __syncthreads();

        // GEMM2: t[128,128] @ W2[128,128]
#pragma unroll
        for (int i = 0; i < 4; i++)
#pragma unroll
            for (int j = 0; j < 8; j++) acc[i][j] = 0.f;
#pragma unroll 4
        for (int k = 0; k < HID; k++) {
            float a[4];
#pragma unroll
            for (int i = 0; i < 4; i++) a[i] = sBuf[(r0 + i) * 132 + k];
            float4 bA = *(const float4*)&sW2[k * HID + c0];
            float4 bB = *(const float4*)&sW2[k * HID + c0 + 4];
            float b[8] = {bA.x, bA.y, bA.z, bA.w, bB.x, bB.y, bB.z, bB.w};
#pragma unroll
            for (int i = 0; i < 4; i++)
#pragma unroll
                for (int j = 0; j < 8; j++) acc[i][j] = fmaf(a[i], b[j], acc[i][j]);
        }
        __syncthreads();
#pragma unroll
        for (int i = 0; i < 4; i++) {
            float cu = sCut[r0 + i];
#pragma unroll
            for (int j = 0; j < 8; j++)
                sBuf[(r0 + i) * 132 + c0 + j] = (acc[i][j] + sB2[c0 + j]) * cu;
        }
        __syncthreads();
    }

    // segmented aggregation: 4 groups x 128 channels, 32 edges per group
    const float* hsrc = NE ? g_nex : g_h;
    int g = tid >> 7;
    int f = tid & 127;
    int e0 = g * 32;
    float accv = 0.f;
    int cur = sDst[e0];
#pragma unroll 1
    for (int b = 0; b < 4; b++) {
        float hb[8];
#pragma unroll
        for (int j = 0; j < 8; j++)
            hb[j] = hsrc[(long)sRow[e0 + b * 8 + j] * HID + f];
#pragma unroll
        for (int j = 0; j < 8; j++) {
            int e = e0 + b * 8 + j;
            int dd = sDst[e];
            if (dd != cur) {
                atomicAdd(&g_agg[(long)cur * HID + f], accv);
                accv = 0.f;
                cur = dd;
            }
            accv = fmaf(hb[j], sBuf[e * 132 + f], accv);
        }
    }
    atomicAdd(&g_agg[(long)cur * HID + f], accv);
}

// ---------------- generic node GEMM: out = base + act(A @ W + bias) ----------------
__device__ __forceinline__ float* selp(int s, float* dout) {
    switch (s) {
        case 0: return g_x;
        case 1: return g_h;
        case 2: return g_h2;
        case 3: return g_agg;
        default: return dout;
    }
}

__global__ void __launch_bounds__(256, 1)
k_ngemm(int Asel, const float* __restrict__ Wg, const float* __restrict__ bias,
        int baseSel, int outSel, int silu, float* dout) {
    extern __shared__ float sm[];
    float* sA = sm;                    // 64 x 132
    float* sW = sA + 64 * 132;         // 128 x 128
    float* sB = sW + HID * HID;        // 128
    const float* A = selp(Asel, dout);
    float* out = selp(outSel, dout);
    const float* base = (baseSel >= 0) ? selp(baseSel, dout) : nullptr;

    int tid = threadIdx.x;
    int rb = blockIdx.x * 64;
    for (int i = tid; i < 64 * HID; i += 256) {
        int r = i >> 7, k = i & 127;
        sA[r * 132 + k] = A[(long)(rb + r) * HID + k];
    }
    for (int i = tid; i < HID * HID; i += 256) sW[i] = Wg[i];
    if (tid < 128) sB[tid] = bias ? bias[tid] : 0.f;
    __syncthreads();

    int tx = tid & 15, ty = tid >> 4;
    int r0 = ty * 4, c0 = tx * 8;
    float acc[4][8];
#pragma unroll
    for (int i = 0; i < 4; i++)
#pragma unroll
        for (int j = 0; j < 8; j++) acc[i][j] = 0.f;
#pragma unroll 4
    for (int k = 0; k < HID; k++) {
        float a[4];
#pragma unroll
        for (int i = 0; i < 4; i++) a[i] = sA[(r0 + i) * 132 + k];
        float4 bA = *(const float4*)&sW[k * HID + c0];
        float4 bB = *(const float4*)&sW[k * HID + c0 + 4];
        float b[8] = {bA.x, bA.y, bA.z, bA.w, bB.x, bB.y, bB.z, bB.w};
#pragma unroll
        for (int i = 0; i < 4; i++)
#pragma unroll
            for (int j = 0; j < 8; j++) acc[i][j] = fmaf(a[i], b[j], acc[i][j]);
    }
#pragma unroll
    for (int i = 0; i < 4; i++) {
        long ro = (long)(rb + r0 + i) * HID;
#pragma unroll
        for (int j = 0; j < 8; j++) {
            float v = acc[i][j] + sB[c0 + j];
            if (silu) v = v / (1.0f + __expf(-v));
            if (base) v += base[ro + c0 + j];
            out[ro + c0 + j] = v;
        }
    }
}

// ---------------- launch ----------------
extern "C" void kernel_launch(void* const* d_in, const int* in_sizes, int n_in,
                              void* d_out, int out_size) {
    const int*   z       = (const int*)d_in[0];
    const int*   ei      = (const int*)d_in[1];
    const float* ew      = (const float*)d_in[2];
    const float* emb     = (const float*)d_in[3];
    const float* neemb   = (const float*)d_in[4];
    const float* neprojw = (const float*)d_in[5];
    const float* neprojb = (const float*)d_in[6];
    const float* necatw  = (const float*)d_in[7];
    const float* necatb  = (const float*)d_in[8];
    const float* means   = (const float*)d_in[9];
    const float* betas   = (const float*)d_in[10];
    const float* mlpw1   = (const float*)d_in[11];
    const float* mlpb1   = (const float*)d_in[12];
    const float* mlpw2   = (const float*)d_in[13];
    const float* mlpb2   = (const float*)d_in[14];
    const float* lin1w   = (const float*)d_in[15];
    const float* lin2w   = (const float*)d_in[16];
    const float* lin2b   = (const float*)d_in[17];
    const float* linw    = (const float*)d_in[18];
    const float* linb    = (const float*)d_in[19];
    float* outp = (float*)d_out;

    const size_t smI = (size_t)(NRBF * HID + HID * HID + 128 * RBF_P + 128 * 132 + 3 * 128) * 4
                       + 2 * 128 * 4;                         // 187,904 B
    const size_t smN = (size_t)(NRBF * HID + 128 * RBF_P + 128 * 132 + 3 * 128) * 4
                       + 2 * 128 * 4;                         // 122,368 B
    const size_t smG = (size_t)(64 * 132 + HID * HID + 128) * 4;  // 99,840 B

    cudaFuncSetAttribute(k_edge<0>, cudaFuncAttributeMaxDynamicSharedMemorySize, (int)smI);
    cudaFuncSetAttribute(k_edge<1>, cudaFuncAttributeMaxDynamicSharedMemorySize, (int)smN);
    cudaFuncSetAttribute(k_ngemm,   cudaFuncAttributeMaxDynamicSharedMemorySize, (int)smG);

    // ---- sort edges by destination + precompute per-edge data ----
    k_zero_cnt<<<NN / 256, 256>>>();
    k_hist<<<EE / 256, 256>>>(ei);
    k_scan<<<1, 1024>>>();
    k_place<<<EE / 256, 256>>>(ei);
    k_build<<<EE / 8, 256>>>(ei, ew, means, betas);
    k_gather<<<NN * HID / 256, 256>>>(z, emb, neemb);

    // ---- NeighborEmbedding ----
    k_zero_agg<<<NN * HID / 256, 256>>>();
    k_edge<1><<<EE / 128, 512, smN>>>(neprojw, neprojb, nullptr, nullptr);
    // x = concat(x, xn) @ ne_cat_w + b  == x@Wtop + xn@Wbot + b
    k_ngemm<<<NN / 64, 256, smG>>>(0, necatw, necatb, -1, 2, 0, outp);               // h2 = x@Wtop + b
    k_ngemm<<<NN / 64, 256, smG>>>(3, necatw + HID * HID, nullptr, 2, 0, 0, outp);   // x = h2 + agg@Wbot

    // ---- interaction layers ----
    for (int l = 0; l < NLAY; l++) {
        k_zero_agg<<<NN * HID / 256, 256>>>();
        k_ngemm<<<NN / 64, 256, smG>>>(0, lin1w + (size_t)l * HID * HID, nullptr, -1, 1, 0, outp);  // h = x@lin1
        k_edge<0><<<EE / 128, 512, smI>>>(mlpw1 + (size_t)l * NRBF * HID, mlpb1 + (size_t)l * HID,
                                          mlpw2 + (size_t)l * HID * HID, mlpb2 + (size_t)l * HID);
        k_ngemm<<<NN / 64, 256, smG>>>(3, lin2w + (size_t)l * HID * HID, lin2b + (size_t)l * HID,
                                       -1, 2, 1, outp);                                              // h2 = silu(agg@lin2+b)
        k_ngemm<<<NN / 64, 256, smG>>>(2, linw + (size_t)l * HID * HID, linb + (size_t)l * HID,
                                       0, (l == NLAY - 1) ? 4 : 0, 0, outp);                         // x(+out) = x + h2@lin + b
    }
}